// round 8
// baseline (speedup 1.0000x reference)
#include <cuda_runtime.h>
#include <cstdint>

#define LN_EPS 1e-5f
#define EPS_ATTN 1e-8f
#define SCALE 0.08838834764831845f
typedef unsigned long long ull;

__device__ __forceinline__ ull fma2(ull a, ull b, ull c){ ull d; asm("fma.rn.f32x2 %0,%1,%2,%3;":"=l"(d):"l"(a),"l"(b),"l"(c)); return d; }
__device__ __forceinline__ ull add2(ull a, ull b){ ull d; asm("add.rn.f32x2 %0,%1,%2;":"=l"(d):"l"(a),"l"(b)); return d; }
__device__ __forceinline__ ull pk2(float lo, float hi){ ull d; asm("mov.b64 %0,{%1,%2};":"=l"(d):"f"(lo),"f"(hi)); return d; }
__device__ __forceinline__ void unpk(ull v, float&lo, float&hi){ asm("mov.b64 {%0,%1},%2;":"=f"(lo),"=f"(hi):"l"(v)); }
__device__ __forceinline__ float up2(ull v){ float a,b; unpk(v,a,b); return a+b; }

__device__ float g_slots_n[131072];
__device__ float g_qk[131072];
__device__ float g_qksum[1024];
__device__ float g_part[8388608];   // [b][64 tiles][8 s][128]
__device__ float g_cs[65536];       // [b][tile][s]
__device__ float g_cb[65536];
// transposed weights
__device__ __align__(16) float g_WihT[49152];  // [128 d][384 j]
__device__ __align__(16) float g_WhhT[49152];
__device__ __align__(16) float g_W1T[32768];   // [128 d][256 j]
__device__ __align__(16) float g_W2T[32768];   // [256 h][128 t]
__device__ __align__(16) float g_WvT[16384];   // [128 d][128 t]
__device__ __align__(16) float g_WqT[16384];

// ---- one-time weight transposes ----
__global__ void k_transpose(const float* __restrict__ Wih, const float* __restrict__ Whh,
                            const float* __restrict__ W1, const float* __restrict__ W2,
                            const float* __restrict__ Wv, const float* __restrict__ Wq){
    int i = blockIdx.x*256 + threadIdx.x;
    if(i < 49152){ int d=i/384, j=i%384; g_WihT[i]=Wih[j*128+d]; return; }
    i -= 49152;
    if(i < 49152){ int d=i/384, j=i%384; g_WhhT[i]=Whh[j*128+d]; return; }
    i -= 49152;
    if(i < 32768){ int d=i/256, j=i%256; g_W1T[i]=W1[j*128+d]; return; }
    i -= 32768;
    if(i < 32768){ int h=i/128, tt=i%128; g_W2T[i]=W2[tt*256+h]; return; }
    i -= 32768;
    if(i < 16384){ int d=i/128, tt=i%128; g_WvT[i]=Wv[tt*128+d]; return; }
    i -= 16384;
    if(i < 16384){ int d=i/128, j=i%128; g_WqT[i]=Wq[j*128+d]; }
}

// ---- group reduction: 256 threads, 2 groups of 128 (4 warps each) ----
__device__ __forceinline__ float gsum4w(float v, int t, volatile float* red){
    #pragma unroll
    for(int o=16;o>0;o>>=1) v += __shfl_xor_sync(0xffffffffu,v,o);
    if((t&31)==0) red[t>>5]=v;
    __syncthreads();
    int base=(t>>7)<<2;
    v = red[base]+red[base+1]+red[base+2]+red[base+3];
    __syncthreads();
    return v;
}

// ---- shared projection: LN(sd) -> slots_n, q = sn@Wq.T, qk = q@Wk, qksum ----
// 256 threads: group g2=t>>7 owns slots 4*g2..+3; thread owns col c=t&127.
// Pair-interleaved smem layouts: SNP/QsP[d*8 + s].
__device__ __forceinline__ void project4(
    int b, int t, int c, int g2, const float* sd,
    float* SNP, float* QsP, volatile float* red, const float* __restrict__ Wk)
{
    int s0=4*g2;
    #pragma unroll
    for(int sl=0;sl<4;sl++){
        float m = gsum4w(sd[sl],t,red)*(1.f/128.f);
        float dv = sd[sl]-m;
        float var = gsum4w(dv*dv,t,red)*(1.f/128.f);
        float sn = dv*rsqrtf(var+LN_EPS);
        SNP[c*8+s0+sl]=sn;
        g_slots_n[(b*8+s0+sl)*128+c]=sn;
    }
    __syncthreads();
    ull q0=0ull,q1=0ull;
    #pragma unroll 8
    for(int d=0;d<128;d++){
        float w=g_WqT[d*128+c]; ull wp=pk2(w,w);
        q0=fma2(wp,*(const ull*)(SNP+d*8+s0),q0);
        q1=fma2(wp,*(const ull*)(SNP+d*8+s0+2),q1);
    }
    {
        float y0,y1,y2,y3; unpk(q0,y0,y1); unpk(q1,y2,y3);
        QsP[c*8+s0]=y0; QsP[c*8+s0+1]=y1; QsP[c*8+s0+2]=y2; QsP[c*8+s0+3]=y3;
    }
    __syncthreads();
    ull k0=0ull,k1=0ull;
    #pragma unroll 8
    for(int d=0;d<128;d++){
        float w=Wk[d*128+c]; ull wp=pk2(w,w);
        k0=fma2(wp,*(const ull*)(QsP+d*8+s0),k0);
        k1=fma2(wp,*(const ull*)(QsP+d*8+s0+2),k1);
    }
    float kk[4]; unpk(k0,kk[0],kk[1]); unpk(k1,kk[2],kk[3]);
    #pragma unroll
    for(int sl=0;sl<4;sl++){
        g_qk[(b*8+s0+sl)*128+c]=kk[sl];
        float qs=gsum4w(kk[sl],t,red);
        if(c==0) g_qksum[b*8+s0+sl]=qs;
    }
}

__global__ void __launch_bounds__(256) k_init_proj(
    const float* __restrict__ noise, const float* __restrict__ mu, const float* __restrict__ ls,
    const float* __restrict__ Wk)
{
    __shared__ __align__(16) float SNP[1024];
    __shared__ __align__(16) float QsP[1024];
    __shared__ volatile float red[8];
    int b=blockIdx.x, t=threadIdx.x, c=t&127, g2=t>>7, s0=4*g2;
    float e=expf(ls[c]), m=mu[c];
    float sd[4];
    #pragma unroll
    for(int sl=0;sl<4;sl++)
        sd[sl]=m+e*noise[(b*8+s0+sl)*128+c];
    project4(b,t,c,g2,sd,SNP,QsP,red,Wk);
}

// ---- attention: grid(64,128) tiles of 64 rows, 256 threads, 3 blocks/SM ----
#define ATTN_SMEM_BYTES 75680
__global__ void __launch_bounds__(256,3) k_attn(const float* __restrict__ inputs){
    extern __shared__ float sm[];
    float* XS  = sm;            // 64*132 = 8448
    float* QK  = sm+8448;       // 1024
    float* LG  = sm+9472;       // 64*9 = 576
    float* AA  = sm+10048;      // 512
    float* QS  = sm+10560;      // 8
    float* MUb = sm+10568;      // 64
    float* RSb = sm+10632;      // 64
    float* CW  = sm+10696;      // 16
    float* CBv = sm+10712;      // 16
    float* PART= sm+10728;      // 8*8*128 = 8192   (total 18920 floats)
    const int t=threadIdx.x, lane=t&31, w=t>>5;
    const int tile=blockIdx.x, b=blockIdx.y;
    const int row=t&63, h=t>>6, sb=2*h;

    { const float4* gsrc=(const float4*)(inputs + ((size_t)b*4096 + tile*64)*128);
      #pragma unroll 8
      for(int j=t;j<2048;j+=256){ int r=j>>5,cc=j&31; *(float4*)(XS+r*132+cc*4)=gsrc[j]; } }
    { int s=t>>5, i=lane*4;
      *(float4*)(QK+s*128+i)=*(const float4*)(g_qk+(b*8+s)*128+i);
      if(t<8) QS[t]=g_qksum[b*8+t]; }
    __syncthreads();

    // phase 2: thread (h,row) computes 2 slot dots; h==0 also computes LN stats
    float at0, at1, mu, rstd;
    {
        ull p0=0ull,p1=0ull,s1=0ull,s2=0ull;
        const ulonglong2* xp=(const ulonglong2*)(XS+row*132);
        const ulonglong2* qa=(const ulonglong2*)(QK+sb*128);
        const ulonglong2* qb=(const ulonglong2*)(QK+(sb+1)*128);
        #pragma unroll 4
        for(int cc=0;cc<32;cc++){
            ulonglong2 xv=xp[cc];
            if(h==0){ s1=add2(s1,xv.x); s1=add2(s1,xv.y);
                      s2=fma2(xv.x,xv.x,s2); s2=fma2(xv.y,xv.y,s2); }
            ulonglong2 qv=qa[cc]; p0=fma2(xv.x,qv.x,p0); p0=fma2(xv.y,qv.y,p0);
            qv=qb[cc]; p1=fma2(xv.x,qv.x,p1); p1=fma2(xv.y,qv.y,p1);
        }
        LG[row*9+sb]=up2(p0); LG[row*9+sb+1]=up2(p1);
        if(h==0){
            float sum=up2(s1), ssq=up2(s2);
            float m_=sum*(1.f/128.f);
            MUb[row]=m_;
            RSb[row]=rsqrtf(ssq*(1.f/128.f)-m_*m_+LN_EPS);
        }
    }
    __syncthreads();
    mu=MUb[row]; rstd=RSb[row];
    {
        float lg[8];
        #pragma unroll
        for(int k=0;k<8;k++) lg[k]=SCALE*rstd*(LG[row*9+k]-mu*QS[k]);
        float m=lg[0];
        #pragma unroll
        for(int k=1;k<8;k++) m=fmaxf(m,lg[k]);
        float e[8], tot=0.f;
        #pragma unroll
        for(int k=0;k<8;k++){ e[k]=__expf(lg[k]-m); tot+=e[k]; }
        float inv=1.f/tot;
        at0=e[sb]*inv+EPS_ATTN;
        at1=e[sb+1]*inv+EPS_ATTN;
        AA[row*8+sb]=at0*rstd;
        AA[row*8+sb+1]=at1*rstd;
    }
    {
        float v0=at0, v1=at1, u0=at0*rstd*mu, u1=at1*rstd*mu;
        #pragma unroll
        for(int o=16;o>0;o>>=1){
            v0+=__shfl_xor_sync(0xffffffffu,v0,o);
            v1+=__shfl_xor_sync(0xffffffffu,v1,o);
            u0+=__shfl_xor_sync(0xffffffffu,u0,o);
            u1+=__shfl_xor_sync(0xffffffffu,u1,o);
        }
        if(lane==0){ CW[w*2]=v0; CW[w*2+1]=v1; CBv[w*2]=u0; CBv[w*2+1]=u1; }
    }
    __syncthreads();

    // phase 3: warp w -> rows [w*8, w*8+8), lane -> cols lane*4..+3
    ull acc[8][2];
    #pragma unroll
    for(int s=0;s<8;s++){ acc[s][0]=0ull; acc[s][1]=0ull; }
    #pragma unroll
    for(int r0=0;r0<8;r0++){
        int r=w*8+r0;
        ulonglong2 xv=*(const ulonglong2*)(XS + r*132 + lane*4);
        const float* a8=AA+r*8;
        float4 alo=*(const float4*)a8, ahi=*(const float4*)(a8+4);
        acc[0][0]=fma2(pk2(alo.x,alo.x),xv.x,acc[0][0]); acc[0][1]=fma2(pk2(alo.x,alo.x),xv.y,acc[0][1]);
        acc[1][0]=fma2(pk2(alo.y,alo.y),xv.x,acc[1][0]); acc[1][1]=fma2(pk2(alo.y,alo.y),xv.y,acc[1][1]);
        acc[2][0]=fma2(pk2(alo.z,alo.z),xv.x,acc[2][0]); acc[2][1]=fma2(pk2(alo.z,alo.z),xv.y,acc[2][1]);
        acc[3][0]=fma2(pk2(alo.w,alo.w),xv.x,acc[3][0]); acc[3][1]=fma2(pk2(alo.w,alo.w),xv.y,acc[3][1]);
        acc[4][0]=fma2(pk2(ahi.x,ahi.x),xv.x,acc[4][0]); acc[4][1]=fma2(pk2(ahi.x,ahi.x),xv.y,acc[4][1]);
        acc[5][0]=fma2(pk2(ahi.y,ahi.y),xv.x,acc[5][0]); acc[5][1]=fma2(pk2(ahi.y,ahi.y),xv.y,acc[5][1]);
        acc[6][0]=fma2(pk2(ahi.z,ahi.z),xv.x,acc[6][0]); acc[6][1]=fma2(pk2(ahi.z,ahi.z),xv.y,acc[6][1]);
        acc[7][0]=fma2(pk2(ahi.w,ahi.w),xv.x,acc[7][0]); acc[7][1]=fma2(pk2(ahi.w,ahi.w),xv.y,acc[7][1]);
    }
    if(t<8){
        int s=t, hh=s>>1, j=s&1;
        g_cs[(b*64+tile)*8+s]=CW[(2*hh)*2+j]+CW[(2*hh+1)*2+j];
        g_cb[(b*64+tile)*8+s]=CBv[(2*hh)*2+j]+CBv[(2*hh+1)*2+j];
    }
    #pragma unroll
    for(int s=0;s<8;s++)
        *(ulonglong2*)(PART+(w*8+s)*128+lane*4)=make_ulonglong2(acc[s][0],acc[s][1]);
    __syncthreads();
    {
        int s=t>>5, c0=lane*4;
        float o0=0.f,o1=0.f,o2=0.f,o3=0.f;
        #pragma unroll
        for(int w8=0;w8<8;w8++){
            const float* pp=PART+(w8*8+s)*128+c0;
            o0+=pp[0]; o1+=pp[1]; o2+=pp[2]; o3+=pp[3];
        }
        *(float4*)(g_part+((size_t)(b*64+tile)*8+s)*128+c0)=make_float4(o0,o1,o2,o3);
    }
}

// ---- fused update + projection: 128 blocks x 256 threads, coalesced WT GEMMs ----
__global__ void __launch_bounds__(256) k_update(
    const float* __restrict__ Wk,
    const float* __restrict__ b_ih, const float* __restrict__ b_hh,
    const float* __restrict__ b1, const float* __restrict__ b2,
    float* __restrict__ out, int last)
{
    __shared__ __align__(16) float TsP[1024];
    __shared__ __align__(16) float UsP[1024];
    __shared__ __align__(16) float HsP[1024];
    __shared__ __align__(16) float LNP[1024];
    __shared__ __align__(16) float QsP[1024];
    __shared__ __align__(16) float H1P[2048];
    __shared__ float CSs[8], CBs[8];
    __shared__ volatile float red[8];
    int b=blockIdx.x, t=threadIdx.x, c=t&127, g2=t>>7, s0=4*g2;

    if(t<8){
        float cs=0.f,cb=0.f;
        #pragma unroll 8
        for(int k=0;k<64;k++){ cs+=g_cs[(b*64+k)*8+t]; cb+=g_cb[(b*64+k)*8+t]; }
        CSs[t]=1.f/cs; CBs[t]=cb;
    }
    float a[4]={0.f,0.f,0.f,0.f};
    {
        const float* p=g_part+(size_t)(b*64)*1024 + s0*128 + c;
        #pragma unroll 4
        for(int k=0;k<64;k++){
            #pragma unroll
            for(int sl=0;sl<4;sl++) a[sl]+=p[(size_t)k*1024 + sl*128];
        }
    }
    float hv[4];
    #pragma unroll
    for(int sl=0;sl<4;sl++) hv[sl]=g_slots_n[(b*8+s0+sl)*128+c];
    __syncthreads();
    #pragma unroll
    for(int sl=0;sl<4;sl++){
        TsP[c*8+s0+sl]=(a[sl]-CBs[s0+sl])*CSs[s0+sl];
        HsP[c*8+s0+sl]=hv[sl];
    }
    __syncthreads();
    // updates = T @ Wv.T  (coalesced WvT, slot-pair fma2)
    {
        ull u0=0ull,u1=0ull;
        #pragma unroll 8
        for(int d=0;d<128;d++){
            float w=g_WvT[d*128+c]; ull wp=pk2(w,w);
            u0=fma2(wp,*(const ull*)(TsP+d*8+s0),u0);
            u1=fma2(wp,*(const ull*)(TsP+d*8+s0+2),u1);
        }
        float y0,y1,y2,y3; unpk(u0,y0,y1); unpk(u1,y2,y3);
        UsP[c*8+s0]=y0; UsP[c*8+s0+1]=y1; UsP[c*8+s0+2]=y2; UsP[c*8+s0+3]=y3;
    }
    __syncthreads();
    // GRU
    float sd[4];
    {
        ull xr[2]={0,0},xz[2]={0,0},xn[2]={0,0},hr[2]={0,0},hz[2]={0,0},hn[2]={0,0};
        #pragma unroll 4
        for(int d=0;d<128;d++){
            ull up0=*(const ull*)(UsP+d*8+s0), up1=*(const ull*)(UsP+d*8+s0+2);
            ull hp0=*(const ull*)(HsP+d*8+s0), hp1=*(const ull*)(HsP+d*8+s0+2);
            float w; ull wp;
            w=g_WihT[d*384+c];     wp=pk2(w,w); xr[0]=fma2(wp,up0,xr[0]); xr[1]=fma2(wp,up1,xr[1]);
            w=g_WihT[d*384+128+c]; wp=pk2(w,w); xz[0]=fma2(wp,up0,xz[0]); xz[1]=fma2(wp,up1,xz[1]);
            w=g_WihT[d*384+256+c]; wp=pk2(w,w); xn[0]=fma2(wp,up0,xn[0]); xn[1]=fma2(wp,up1,xn[1]);
            w=g_WhhT[d*384+c];     wp=pk2(w,w); hr[0]=fma2(wp,hp0,hr[0]); hr[1]=fma2(wp,hp1,hr[1]);
            w=g_WhhT[d*384+128+c]; wp=pk2(w,w); hz[0]=fma2(wp,hp0,hz[0]); hz[1]=fma2(wp,hp1,hz[1]);
            w=g_WhhT[d*384+256+c]; wp=pk2(w,w); hn[0]=fma2(wp,hp0,hn[0]); hn[1]=fma2(wp,hp1,hn[1]);
        }
        float XR[4],XZ[4],XN[4],HR[4],HZ[4],HN[4];
        unpk(xr[0],XR[0],XR[1]); unpk(xr[1],XR[2],XR[3]);
        unpk(xz[0],XZ[0],XZ[1]); unpk(xz[1],XZ[2],XZ[3]);
        unpk(xn[0],XN[0],XN[1]); unpk(xn[1],XN[2],XN[3]);
        unpk(hr[0],HR[0],HR[1]); unpk(hr[1],HR[2],HR[3]);
        unpk(hz[0],HZ[0],HZ[1]); unpk(hz[1],HZ[2],HZ[3]);
        unpk(hn[0],HN[0],HN[1]); unpk(hn[1],HN[2],HN[3]);
        float bir=b_ih[c], biz=b_ih[128+c], bin=b_ih[256+c];
        float bhr=b_hh[c], bhz=b_hh[128+c], bhn=b_hh[256+c];
        #pragma unroll
        for(int sl=0;sl<4;sl++){
            float rr=1.f/(1.f+__expf(-(XR[sl]+bir+HR[sl]+bhr)));
            float zz=1.f/(1.f+__expf(-(XZ[sl]+biz+HZ[sl]+bhz)));
            float nn=tanhf(XN[sl]+bin+rr*(HN[sl]+bhn));
            sd[sl]=(1.f-zz)*nn+zz*hv[sl];
        }
    }
    // LN(sd) for MLP
    #pragma unroll
    for(int sl=0;sl<4;sl++){
        float m=gsum4w(sd[sl],t,red)*(1.f/128.f);
        float dv=sd[sl]-m;
        float var=gsum4w(dv*dv,t,red)*(1.f/128.f);
        LNP[c*8+s0+sl]=dv*rsqrtf(var+LN_EPS);
    }
    __syncthreads();
    // H1 = relu(LN @ W1.T + b1): thread owns hidden cols {2c, 2c+1}
    {
        ull A[4]={0,0,0,0};
        #pragma unroll 4
        for(int d=0;d<128;d++){
            ull w=*(const ull*)(g_W1T+d*256+2*c);
            #pragma unroll
            for(int sl=0;sl<4;sl++){
                float x=LNP[d*8+s0+sl];
                A[sl]=fma2(w,pk2(x,x),A[sl]);
            }
        }
        float bb0=b1[2*c], bb1=b1[2*c+1];
        #pragma unroll
        for(int sl=0;sl<4;sl++){
            float y0,y1; unpk(A[sl],y0,y1);
            H1P[(2*c)*8+s0+sl]  =fmaxf(y0+bb0,0.f);
            H1P[(2*c+1)*8+s0+sl]=fmaxf(y1+bb1,0.f);
        }
    }
    __syncthreads();
    // o = sd + H1 @ W2.T + b2
    float o[4];
    {
        ull O0=0ull,O1=0ull;
        #pragma unroll 8
        for(int h=0;h<256;h++){
            float w=g_W2T[h*128+c]; ull wp=pk2(w,w);
            O0=fma2(wp,*(const ull*)(H1P+h*8+s0),O0);
            O1=fma2(wp,*(const ull*)(H1P+h*8+s0+2),O1);
        }
        float y0,y1,y2,y3; unpk(O0,y0,y1); unpk(O1,y2,y3);
        float bb=b2[c];
        o[0]=sd[0]+bb+y0; o[1]=sd[1]+bb+y1; o[2]=sd[2]+bb+y2; o[3]=sd[3]+bb+y3;
    }
    #pragma unroll
    for(int sl=0;sl<4;sl++) out[(b*8+s0+sl)*128+c]=o[sl];
    __syncthreads();
    if(!last) project4(b,t,c,g2,o,LNP,QsP,red,Wk);   // LNP reused as SNP
}

extern "C" void kernel_launch(void* const* d_in, const int* in_sizes, int n_in,
                              void* d_out, int out_size){
    const float* inputs=(const float*)d_in[0];
    const float* noise =(const float*)d_in[1];
    const float* smu   =(const float*)d_in[2];
    const float* sls   =(const float*)d_in[3];
    const float* Wq    =(const float*)d_in[4];
    const float* Wk    =(const float*)d_in[5];
    const float* Wv    =(const float*)d_in[6];
    const float* W_ih  =(const float*)d_in[7];
    const float* W_hh  =(const float*)d_in[8];
    const float* b_ih  =(const float*)d_in[9];
    const float* b_hh  =(const float*)d_in[10];
    const float* W1    =(const float*)d_in[11];
    const float* b1    =(const float*)d_in[12];
    const float* W2    =(const float*)d_in[13];
    const float* b2    =(const float*)d_in[14];
    float* out=(float*)d_out;

    cudaFuncSetAttribute(k_attn, cudaFuncAttributeMaxDynamicSharedMemorySize, ATTN_SMEM_BYTES);

    k_transpose<<<768,256>>>(W_ih,W_hh,W1,W2,Wv,Wq);
    k_init_proj<<<128,256>>>(noise,smu,sls,Wk);
    for(int it=0; it<3; it++){
        dim3 g(64,128);
        k_attn<<<g,256,ATTN_SMEM_BYTES>>>(inputs);
        k_update<<<128,256>>>(Wk,b_ih,b_hh,b1,b2,out, it==2);
    }
}

// round 9
// speedup vs baseline: 1.0007x; 1.0007x over previous
#include <cuda_runtime.h>
#include <cstdint>

#define LN_EPS 1e-5f
#define EPS_ATTN 1e-8f
#define SCALE 0.08838834764831845f
typedef unsigned long long ull;

__device__ __forceinline__ ull fma2(ull a, ull b, ull c){ ull d; asm("fma.rn.f32x2 %0,%1,%2,%3;":"=l"(d):"l"(a),"l"(b),"l"(c)); return d; }
__device__ __forceinline__ ull add2(ull a, ull b){ ull d; asm("add.rn.f32x2 %0,%1,%2;":"=l"(d):"l"(a),"l"(b)); return d; }
__device__ __forceinline__ ull pk2(float lo, float hi){ ull d; asm("mov.b64 %0,{%1,%2};":"=l"(d):"f"(lo),"f"(hi)); return d; }
__device__ __forceinline__ void unpk(ull v, float&lo, float&hi){ asm("mov.b64 {%0,%1},%2;":"=f"(lo),"=f"(hi):"l"(v)); }
__device__ __forceinline__ float up2(ull v){ float a,b; unpk(v,a,b); return a+b; }

__device__ float g_slots_n[131072];
__device__ float g_qk[131072];
__device__ float g_qksum[1024];
__device__ float g_part[8388608];   // [b][64 tiles][8 s][128]
__device__ float g_cs[65536];       // [b][tile][s]
__device__ float g_cb[65536];
// transposed weights
__device__ __align__(16) float g_WihT[49152];  // [128 d][384 j]
__device__ __align__(16) float g_WhhT[49152];
__device__ __align__(16) float g_W1T[32768];   // [128 d][256 j]
__device__ __align__(16) float g_W2T[32768];   // [256 h][128 t]
__device__ __align__(16) float g_WvT[16384];   // [128 d][128 t]
__device__ __align__(16) float g_WqT[16384];

// ---- one-time weight transposes ----
__global__ void k_transpose(const float* __restrict__ Wih, const float* __restrict__ Whh,
                            const float* __restrict__ W1, const float* __restrict__ W2,
                            const float* __restrict__ Wv, const float* __restrict__ Wq){
    int i = blockIdx.x*256 + threadIdx.x;
    if(i < 49152){ int d=i/384, j=i%384; g_WihT[i]=Wih[j*128+d]; return; }
    i -= 49152;
    if(i < 49152){ int d=i/384, j=i%384; g_WhhT[i]=Whh[j*128+d]; return; }
    i -= 49152;
    if(i < 32768){ int d=i/256, j=i%256; g_W1T[i]=W1[j*128+d]; return; }
    i -= 32768;
    if(i < 32768){ int h=i/128, tt=i%128; g_W2T[i]=W2[tt*256+h]; return; }
    i -= 32768;
    if(i < 16384){ int d=i/128, tt=i%128; g_WvT[i]=Wv[tt*128+d]; return; }
    i -= 16384;
    if(i < 16384){ int d=i/128, j=i%128; g_WqT[i]=Wq[j*128+d]; }
}

// ---- group reduction: 256 threads, 2 groups of 128 (4 warps each) ----
__device__ __forceinline__ float gsum4w(float v, int t, volatile float* red){
    #pragma unroll
    for(int o=16;o>0;o>>=1) v += __shfl_xor_sync(0xffffffffu,v,o);
    if((t&31)==0) red[t>>5]=v;
    __syncthreads();
    int base=(t>>7)<<2;
    v = red[base]+red[base+1]+red[base+2]+red[base+3];
    __syncthreads();
    return v;
}

// ---- shared projection: LN(sd) -> slots_n, q = sn@Wq.T, qk = q@Wk, qksum ----
// 256 threads: group g2=t>>7 owns slots 4*g2..+3; thread owns col c=t&127.
// Pair-interleaved smem layouts: SNP/QsP[d*8 + s].
__device__ __forceinline__ void project4(
    int b, int t, int c, int g2, const float* sd,
    float* SNP, float* QsP, volatile float* red, const float* __restrict__ Wk)
{
    int s0=4*g2;
    #pragma unroll
    for(int sl=0;sl<4;sl++){
        float m = gsum4w(sd[sl],t,red)*(1.f/128.f);
        float dv = sd[sl]-m;
        float var = gsum4w(dv*dv,t,red)*(1.f/128.f);
        float sn = dv*rsqrtf(var+LN_EPS);
        SNP[c*8+s0+sl]=sn;
        g_slots_n[(b*8+s0+sl)*128+c]=sn;
    }
    __syncthreads();
    ull q0=0ull,q1=0ull;
    #pragma unroll 8
    for(int d=0;d<128;d++){
        float w=g_WqT[d*128+c]; ull wp=pk2(w,w);
        q0=fma2(wp,*(const ull*)(SNP+d*8+s0),q0);
        q1=fma2(wp,*(const ull*)(SNP+d*8+s0+2),q1);
    }
    {
        float y0,y1,y2,y3; unpk(q0,y0,y1); unpk(q1,y2,y3);
        QsP[c*8+s0]=y0; QsP[c*8+s0+1]=y1; QsP[c*8+s0+2]=y2; QsP[c*8+s0+3]=y3;
    }
    __syncthreads();
    ull k0=0ull,k1=0ull;
    #pragma unroll 8
    for(int d=0;d<128;d++){
        float w=Wk[d*128+c]; ull wp=pk2(w,w);
        k0=fma2(wp,*(const ull*)(QsP+d*8+s0),k0);
        k1=fma2(wp,*(const ull*)(QsP+d*8+s0+2),k1);
    }
    float kk[4]; unpk(k0,kk[0],kk[1]); unpk(k1,kk[2],kk[3]);
    #pragma unroll
    for(int sl=0;sl<4;sl++){
        g_qk[(b*8+s0+sl)*128+c]=kk[sl];
        float qs=gsum4w(kk[sl],t,red);
        if(c==0) g_qksum[b*8+s0+sl]=qs;
    }
}

__global__ void __launch_bounds__(256) k_init_proj(
    const float* __restrict__ noise, const float* __restrict__ mu, const float* __restrict__ ls,
    const float* __restrict__ Wk)
{
    __shared__ __align__(16) float SNP[1024];
    __shared__ __align__(16) float QsP[1024];
    __shared__ volatile float red[8];
    int b=blockIdx.x, t=threadIdx.x, c=t&127, g2=t>>7, s0=4*g2;
    float e=expf(ls[c]), m=mu[c];
    float sd[4];
    #pragma unroll
    for(int sl=0;sl<4;sl++)
        sd[sl]=m+e*noise[(b*8+s0+sl)*128+c];
    project4(b,t,c,g2,sd,SNP,QsP,red,Wk);
}

// ---- attention: grid(64,128) tiles of 64 rows, 256 threads, 3 blocks/SM ----
#define ATTN_SMEM_BYTES 75680
__global__ void __launch_bounds__(256,3) k_attn(const float* __restrict__ inputs){
    extern __shared__ float sm[];
    float* XS  = sm;            // 64*132 = 8448
    float* QK  = sm+8448;       // 1024
    float* LG  = sm+9472;       // 64*9 = 576
    float* AA  = sm+10048;      // 512
    float* QS  = sm+10560;      // 8
    float* MUb = sm+10568;      // 64
    float* RSb = sm+10632;      // 64
    float* CW  = sm+10696;      // 16
    float* CBv = sm+10712;      // 16
    float* PART= sm+10728;      // 8*8*128 = 8192   (total 18920 floats)
    const int t=threadIdx.x, lane=t&31, w=t>>5;
    const int tile=blockIdx.x, b=blockIdx.y;
    const int row=t&63, h=t>>6, sb=2*h;

    { const float4* gsrc=(const float4*)(inputs + ((size_t)b*4096 + tile*64)*128);
      #pragma unroll 8
      for(int j=t;j<2048;j+=256){ int r=j>>5,cc=j&31; *(float4*)(XS+r*132+cc*4)=gsrc[j]; } }
    { int s=t>>5, i=lane*4;
      *(float4*)(QK+s*128+i)=*(const float4*)(g_qk+(b*8+s)*128+i);
      if(t<8) QS[t]=g_qksum[b*8+t]; }
    __syncthreads();

    // phase 2: thread (h,row) computes 2 slot dots; h==0 also computes LN stats
    float at0, at1, mu, rstd;
    {
        ull p0=0ull,p1=0ull,s1=0ull,s2=0ull;
        const ulonglong2* xp=(const ulonglong2*)(XS+row*132);
        const ulonglong2* qa=(const ulonglong2*)(QK+sb*128);
        const ulonglong2* qb=(const ulonglong2*)(QK+(sb+1)*128);
        #pragma unroll 4
        for(int cc=0;cc<32;cc++){
            ulonglong2 xv=xp[cc];
            if(h==0){ s1=add2(s1,xv.x); s1=add2(s1,xv.y);
                      s2=fma2(xv.x,xv.x,s2); s2=fma2(xv.y,xv.y,s2); }
            ulonglong2 qv=qa[cc]; p0=fma2(xv.x,qv.x,p0); p0=fma2(xv.y,qv.y,p0);
            qv=qb[cc]; p1=fma2(xv.x,qv.x,p1); p1=fma2(xv.y,qv.y,p1);
        }
        LG[row*9+sb]=up2(p0); LG[row*9+sb+1]=up2(p1);
        if(h==0){
            float sum=up2(s1), ssq=up2(s2);
            float m_=sum*(1.f/128.f);
            MUb[row]=m_;
            RSb[row]=rsqrtf(ssq*(1.f/128.f)-m_*m_+LN_EPS);
        }
    }
    __syncthreads();
    mu=MUb[row]; rstd=RSb[row];
    {
        float lg[8];
        #pragma unroll
        for(int k=0;k<8;k++) lg[k]=SCALE*rstd*(LG[row*9+k]-mu*QS[k]);
        float m=lg[0];
        #pragma unroll
        for(int k=1;k<8;k++) m=fmaxf(m,lg[k]);
        float e[8], tot=0.f;
        #pragma unroll
        for(int k=0;k<8;k++){ e[k]=__expf(lg[k]-m); tot+=e[k]; }
        float inv=1.f/tot;
        at0=e[sb]*inv+EPS_ATTN;
        at1=e[sb+1]*inv+EPS_ATTN;
        AA[row*8+sb]=at0*rstd;
        AA[row*8+sb+1]=at1*rstd;
    }
    {
        float v0=at0, v1=at1, u0=at0*rstd*mu, u1=at1*rstd*mu;
        #pragma unroll
        for(int o=16;o>0;o>>=1){
            v0+=__shfl_xor_sync(0xffffffffu,v0,o);
            v1+=__shfl_xor_sync(0xffffffffu,v1,o);
            u0+=__shfl_xor_sync(0xffffffffu,u0,o);
            u1+=__shfl_xor_sync(0xffffffffu,u1,o);
        }
        if(lane==0){ CW[w*2]=v0; CW[w*2+1]=v1; CBv[w*2]=u0; CBv[w*2+1]=u1; }
    }
    __syncthreads();

    // phase 3: warp w -> rows [w*8, w*8+8), lane -> cols lane*4..+3
    ull acc[8][2];
    #pragma unroll
    for(int s=0;s<8;s++){ acc[s][0]=0ull; acc[s][1]=0ull; }
    #pragma unroll
    for(int r0=0;r0<8;r0++){
        int r=w*8+r0;
        ulonglong2 xv=*(const ulonglong2*)(XS + r*132 + lane*4);
        const float* a8=AA+r*8;
        float4 alo=*(const float4*)a8, ahi=*(const float4*)(a8+4);
        acc[0][0]=fma2(pk2(alo.x,alo.x),xv.x,acc[0][0]); acc[0][1]=fma2(pk2(alo.x,alo.x),xv.y,acc[0][1]);
        acc[1][0]=fma2(pk2(alo.y,alo.y),xv.x,acc[1][0]); acc[1][1]=fma2(pk2(alo.y,alo.y),xv.y,acc[1][1]);
        acc[2][0]=fma2(pk2(alo.z,alo.z),xv.x,acc[2][0]); acc[2][1]=fma2(pk2(alo.z,alo.z),xv.y,acc[2][1]);
        acc[3][0]=fma2(pk2(alo.w,alo.w),xv.x,acc[3][0]); acc[3][1]=fma2(pk2(alo.w,alo.w),xv.y,acc[3][1]);
        acc[4][0]=fma2(pk2(ahi.x,ahi.x),xv.x,acc[4][0]); acc[4][1]=fma2(pk2(ahi.x,ahi.x),xv.y,acc[4][1]);
        acc[5][0]=fma2(pk2(ahi.y,ahi.y),xv.x,acc[5][0]); acc[5][1]=fma2(pk2(ahi.y,ahi.y),xv.y,acc[5][1]);
        acc[6][0]=fma2(pk2(ahi.z,ahi.z),xv.x,acc[6][0]); acc[6][1]=fma2(pk2(ahi.z,ahi.z),xv.y,acc[6][1]);
        acc[7][0]=fma2(pk2(ahi.w,ahi.w),xv.x,acc[7][0]); acc[7][1]=fma2(pk2(ahi.w,ahi.w),xv.y,acc[7][1]);
    }
    if(t<8){
        int s=t, hh=s>>1, j=s&1;
        g_cs[(b*64+tile)*8+s]=CW[(2*hh)*2+j]+CW[(2*hh+1)*2+j];
        g_cb[(b*64+tile)*8+s]=CBv[(2*hh)*2+j]+CBv[(2*hh+1)*2+j];
    }
    #pragma unroll
    for(int s=0;s<8;s++)
        *(ulonglong2*)(PART+(w*8+s)*128+lane*4)=make_ulonglong2(acc[s][0],acc[s][1]);
    __syncthreads();
    {
        int s=t>>5, c0=lane*4;
        float o0=0.f,o1=0.f,o2=0.f,o3=0.f;
        #pragma unroll
        for(int w8=0;w8<8;w8++){
            const float* pp=PART+(w8*8+s)*128+c0;
            o0+=pp[0]; o1+=pp[1]; o2+=pp[2]; o3+=pp[3];
        }
        *(float4*)(g_part+((size_t)(b*64+tile)*8+s)*128+c0)=make_float4(o0,o1,o2,o3);
    }
}

// ---- fused update + projection: 128 blocks x 256 threads, coalesced WT GEMMs ----
__global__ void __launch_bounds__(256) k_update(
    const float* __restrict__ Wk,
    const float* __restrict__ b_ih, const float* __restrict__ b_hh,
    const float* __restrict__ b1, const float* __restrict__ b2,
    float* __restrict__ out, int last)
{
    __shared__ __align__(16) float TsP[1024];
    __shared__ __align__(16) float UsP[1024];
    __shared__ __align__(16) float HsP[1024];
    __shared__ __align__(16) float LNP[1024];
    __shared__ __align__(16) float QsP[1024];
    __shared__ __align__(16) float H1P[2048];
    __shared__ float CSs[8], CBs[8];
    __shared__ volatile float red[8];
    int b=blockIdx.x, t=threadIdx.x, c=t&127, g2=t>>7, s0=4*g2;

    if(t<8){
        float cs=0.f,cb=0.f;
        #pragma unroll 8
        for(int k=0;k<64;k++){ cs+=g_cs[(b*64+k)*8+t]; cb+=g_cb[(b*64+k)*8+t]; }
        CSs[t]=1.f/cs; CBs[t]=cb;
    }
    float a[4]={0.f,0.f,0.f,0.f};
    {
        const float* p=g_part+(size_t)(b*64)*1024 + s0*128 + c;
        #pragma unroll 4
        for(int k=0;k<64;k++){
            #pragma unroll
            for(int sl=0;sl<4;sl++) a[sl]+=p[(size_t)k*1024 + sl*128];
        }
    }
    float hv[4];
    #pragma unroll
    for(int sl=0;sl<4;sl++) hv[sl]=g_slots_n[(b*8+s0+sl)*128+c];
    __syncthreads();
    #pragma unroll
    for(int sl=0;sl<4;sl++){
        TsP[c*8+s0+sl]=(a[sl]-CBs[s0+sl])*CSs[s0+sl];
        HsP[c*8+s0+sl]=hv[sl];
    }
    __syncthreads();
    // updates = T @ Wv.T  (coalesced WvT, slot-pair fma2)
    {
        ull u0=0ull,u1=0ull;
        #pragma unroll 8
        for(int d=0;d<128;d++){
            float w=g_WvT[d*128+c]; ull wp=pk2(w,w);
            u0=fma2(wp,*(const ull*)(TsP+d*8+s0),u0);
            u1=fma2(wp,*(const ull*)(TsP+d*8+s0+2),u1);
        }
        float y0,y1,y2,y3; unpk(u0,y0,y1); unpk(u1,y2,y3);
        UsP[c*8+s0]=y0; UsP[c*8+s0+1]=y1; UsP[c*8+s0+2]=y2; UsP[c*8+s0+3]=y3;
    }
    __syncthreads();
    // GRU
    float sd[4];
    {
        ull xr[2]={0,0},xz[2]={0,0},xn[2]={0,0},hr[2]={0,0},hz[2]={0,0},hn[2]={0,0};
        #pragma unroll 4
        for(int d=0;d<128;d++){
            ull up0=*(const ull*)(UsP+d*8+s0), up1=*(const ull*)(UsP+d*8+s0+2);
            ull hp0=*(const ull*)(HsP+d*8+s0), hp1=*(const ull*)(HsP+d*8+s0+2);
            float w; ull wp;
            w=g_WihT[d*384+c];     wp=pk2(w,w); xr[0]=fma2(wp,up0,xr[0]); xr[1]=fma2(wp,up1,xr[1]);
            w=g_WihT[d*384+128+c]; wp=pk2(w,w); xz[0]=fma2(wp,up0,xz[0]); xz[1]=fma2(wp,up1,xz[1]);
            w=g_WihT[d*384+256+c]; wp=pk2(w,w); xn[0]=fma2(wp,up0,xn[0]); xn[1]=fma2(wp,up1,xn[1]);
            w=g_WhhT[d*384+c];     wp=pk2(w,w); hr[0]=fma2(wp,hp0,hr[0]); hr[1]=fma2(wp,hp1,hr[1]);
            w=g_WhhT[d*384+128+c]; wp=pk2(w,w); hz[0]=fma2(wp,hp0,hz[0]); hz[1]=fma2(wp,hp1,hz[1]);
            w=g_WhhT[d*384+256+c]; wp=pk2(w,w); hn[0]=fma2(wp,hp0,hn[0]); hn[1]=fma2(wp,hp1,hn[1]);
        }
        float XR[4],XZ[4],XN[4],HR[4],HZ[4],HN[4];
        unpk(xr[0],XR[0],XR[1]); unpk(xr[1],XR[2],XR[3]);
        unpk(xz[0],XZ[0],XZ[1]); unpk(xz[1],XZ[2],XZ[3]);
        unpk(xn[0],XN[0],XN[1]); unpk(xn[1],XN[2],XN[3]);
        unpk(hr[0],HR[0],HR[1]); unpk(hr[1],HR[2],HR[3]);
        unpk(hz[0],HZ[0],HZ[1]); unpk(hz[1],HZ[2],HZ[3]);
        unpk(hn[0],HN[0],HN[1]); unpk(hn[1],HN[2],HN[3]);
        float bir=b_ih[c], biz=b_ih[128+c], bin=b_ih[256+c];
        float bhr=b_hh[c], bhz=b_hh[128+c], bhn=b_hh[256+c];
        #pragma unroll
        for(int sl=0;sl<4;sl++){
            float rr=1.f/(1.f+__expf(-(XR[sl]+bir+HR[sl]+bhr)));
            float zz=1.f/(1.f+__expf(-(XZ[sl]+biz+HZ[sl]+bhz)));
            float nn=tanhf(XN[sl]+bin+rr*(HN[sl]+bhn));
            sd[sl]=(1.f-zz)*nn+zz*hv[sl];
        }
    }
    // LN(sd) for MLP
    #pragma unroll
    for(int sl=0;sl<4;sl++){
        float m=gsum4w(sd[sl],t,red)*(1.f/128.f);
        float dv=sd[sl]-m;
        float var=gsum4w(dv*dv,t,red)*(1.f/128.f);
        LNP[c*8+s0+sl]=dv*rsqrtf(var+LN_EPS);
    }
    __syncthreads();
    // H1 = relu(LN @ W1.T + b1): thread owns hidden cols {2c, 2c+1}
    {
        ull A[4]={0,0,0,0};
        #pragma unroll 4
        for(int d=0;d<128;d++){
            ull w=*(const ull*)(g_W1T+d*256+2*c);
            #pragma unroll
            for(int sl=0;sl<4;sl++){
                float x=LNP[d*8+s0+sl];
                A[sl]=fma2(w,pk2(x,x),A[sl]);
            }
        }
        float bb0=b1[2*c], bb1=b1[2*c+1];
        #pragma unroll
        for(int sl=0;sl<4;sl++){
            float y0,y1; unpk(A[sl],y0,y1);
            H1P[(2*c)*8+s0+sl]  =fmaxf(y0+bb0,0.f);
            H1P[(2*c+1)*8+s0+sl]=fmaxf(y1+bb1,0.f);
        }
    }
    __syncthreads();
    // o = sd + H1 @ W2.T + b2
    float o[4];
    {
        ull O0=0ull,O1=0ull;
        #pragma unroll 8
        for(int h=0;h<256;h++){
            float w=g_W2T[h*128+c]; ull wp=pk2(w,w);
            O0=fma2(wp,*(const ull*)(H1P+h*8+s0),O0);
            O1=fma2(wp,*(const ull*)(H1P+h*8+s0+2),O1);
        }
        float y0,y1,y2,y3; unpk(O0,y0,y1); unpk(O1,y2,y3);
        float bb=b2[c];
        o[0]=sd[0]+bb+y0; o[1]=sd[1]+bb+y1; o[2]=sd[2]+bb+y2; o[3]=sd[3]+bb+y3;
    }
    #pragma unroll
    for(int sl=0;sl<4;sl++) out[(b*8+s0+sl)*128+c]=o[sl];
    __syncthreads();
    if(!last) project4(b,t,c,g2,o,LNP,QsP,red,Wk);   // LNP reused as SNP
}

extern "C" void kernel_launch(void* const* d_in, const int* in_sizes, int n_in,
                              void* d_out, int out_size){
    const float* inputs=(const float*)d_in[0];
    const float* noise =(const float*)d_in[1];
    const float* smu   =(const float*)d_in[2];
    const float* sls   =(const float*)d_in[3];
    const float* Wq    =(const float*)d_in[4];
    const float* Wk    =(const float*)d_in[5];
    const float* Wv    =(const float*)d_in[6];
    const float* W_ih  =(const float*)d_in[7];
    const float* W_hh  =(const float*)d_in[8];
    const float* b_ih  =(const float*)d_in[9];
    const float* b_hh  =(const float*)d_in[10];
    const float* W1    =(const float*)d_in[11];
    const float* b1    =(const float*)d_in[12];
    const float* W2    =(const float*)d_in[13];
    const float* b2    =(const float*)d_in[14];
    float* out=(float*)d_out;

    cudaFuncSetAttribute(k_attn, cudaFuncAttributeMaxDynamicSharedMemorySize, ATTN_SMEM_BYTES);

    k_transpose<<<768,256>>>(W_ih,W_hh,W1,W2,Wv,Wq);
    k_init_proj<<<128,256>>>(noise,smu,sls,Wk);
    for(int it=0; it<3; it++){
        dim3 g(64,128);
        k_attn<<<g,256,ATTN_SMEM_BYTES>>>(inputs);
        k_update<<<128,256>>>(Wk,b_ih,b_hh,b1,b2,out, it==2);
    }
}